// round 3
// baseline (speedup 1.0000x reference)
#include <cuda_runtime.h>

// SSIM-style loss (sum over channels+window, /ws^2), single fused kernel.
// x, y: (32, 3, 512, 512) fp32. out: (32,) fp32.
//
// One CTA per (batch, window-row): 1024 CTAs x 128 threads, single wave
// (7 CTAs/SM, regs capped <=73 via launch_bounds(128,7)).
// Thread t owns float4-column t over 16 rows x 3 channels.
// Loads batched 8 rows deep (16 LDG.128 in flight per thread) with __ldcs
// streaming hints -> maximize DRAM MLP for a touch-once stream.
// Per-batch ticket: last CTA of each batch folds 32 partials -> out[b].

#define IMG_H 512
#define IMG_W 512
#define NCH 3
#define WS 16
#define NWIN_X 32
#define NWIN_Y 32
#define NBATCH 32
#define W4 (IMG_W / 4)

static __device__ float        g_partial[NBATCH * NWIN_Y];
static __device__ unsigned int g_ticket[NBATCH];

__global__ __launch_bounds__(128, 7)
void ssim_fused_kernel(const float* __restrict__ x, const float* __restrict__ y,
                       float* __restrict__ out) {
    const int t  = threadIdx.x;            // float4 column 0..127
    const int br = blockIdx.x & 31;        // window row
    const int b  = blockIdx.x >> 5;        // batch

    const size_t img = (size_t)NCH * IMG_H * IMG_W;
    const float4* __restrict__ xp = (const float4*)(x + (size_t)b * img);
    const float4* __restrict__ yp = (const float4*)(y + (size_t)b * img);

    float sx = 0.f, sy = 0.f, sxx = 0.f, syy = 0.f, sxy = 0.f;

#pragma unroll
    for (int c = 0; c < NCH; ++c) {
        size_t base = (size_t)c * (IMG_H * W4) + (size_t)(br * WS) * W4 + t;
#pragma unroll
        for (int h0 = 0; h0 < WS; h0 += 8) {
            float4 vx[8], vy[8];
#pragma unroll
            for (int j = 0; j < 8; ++j)
                vx[j] = __ldcs(xp + base + (size_t)(h0 + j) * W4);
#pragma unroll
            for (int j = 0; j < 8; ++j)
                vy[j] = __ldcs(yp + base + (size_t)(h0 + j) * W4);
#pragma unroll
            for (int j = 0; j < 8; ++j) {
                sx += (vx[j].x + vx[j].y) + (vx[j].z + vx[j].w);
                sy += (vy[j].x + vy[j].y) + (vy[j].z + vy[j].w);
                sxx = fmaf(vx[j].x, vx[j].x, sxx); sxx = fmaf(vx[j].y, vx[j].y, sxx);
                sxx = fmaf(vx[j].z, vx[j].z, sxx); sxx = fmaf(vx[j].w, vx[j].w, sxx);
                syy = fmaf(vy[j].x, vy[j].x, syy); syy = fmaf(vy[j].y, vy[j].y, syy);
                syy = fmaf(vy[j].z, vy[j].z, syy); syy = fmaf(vy[j].w, vy[j].w, syy);
                sxy = fmaf(vx[j].x, vy[j].x, sxy); sxy = fmaf(vx[j].y, vy[j].y, sxy);
                sxy = fmaf(vx[j].z, vy[j].z, sxy); sxy = fmaf(vx[j].w, vy[j].w, sxy);
            }
        }
    }

    // fold 4 adjacent threads (one 16-col window)
#pragma unroll
    for (int off = 1; off < 4; off <<= 1) {
        sx  += __shfl_xor_sync(0xffffffffu, sx,  off);
        sy  += __shfl_xor_sync(0xffffffffu, sy,  off);
        sxx += __shfl_xor_sync(0xffffffffu, sxx, off);
        syy += __shfl_xor_sync(0xffffffffu, syy, off);
        sxy += __shfl_xor_sync(0xffffffffu, sxy, off);
    }

    __shared__ float s_ssim[NWIN_X];
    __shared__ unsigned int s_ticket;
    if ((t & 3) == 0) {
        const float inv = 1.0f / (WS * WS);
        const float C1 = 6.5025f;
        const float C2 = 58.5225f;
        float mx = sx * inv, my = sy * inv;
        float vx = sxx * inv - mx * mx;
        float vy = syy * inv - my * my;
        float cv = sxy * inv - mx * my;
        float num = (2.0f * mx * my + C1) * (2.0f * cv + C2);
        float den = (mx * mx + my * my + C1) * (vx + vy + C2);
        s_ssim[t >> 2] = num / den;
    }
    __syncthreads();

    if (t < 32) {
        float v = s_ssim[t];
#pragma unroll
        for (int off = 16; off; off >>= 1)
            v += __shfl_xor_sync(0xffffffffu, v, off);
        if (t == 0) {
            g_partial[blockIdx.x] = v;
            __threadfence();
            unsigned int tk = atomicAdd(&g_ticket[b], 1u);
            s_ticket = tk;
        }
    }
    __syncthreads();

    // Last CTA of this batch folds the 32 row-partials.
    if (s_ticket == NWIN_Y - 1) {
        if (t < 32) {
            volatile float* vp = (volatile float*)&g_partial[b * NWIN_Y];
            float v = vp[t];
#pragma unroll
            for (int off = 16; off; off >>= 1)
                v += __shfl_xor_sync(0xffffffffu, v, off);
            if (t == 0) {
                out[b] = (1.0f - v * (1.0f / (NWIN_X * NWIN_Y))) * 0.5f;
                g_ticket[b] = 0u;   // reset for next (graph-replayed) launch
            }
        }
    }
}

extern "C" void kernel_launch(void* const* d_in, const int* in_sizes, int n_in,
                              void* d_out, int out_size) {
    const float* x = (const float*)d_in[0];
    const float* y = (const float*)d_in[1];
    float* out = (float*)d_out;
    (void)in_sizes; (void)n_in; (void)out_size;

    ssim_fused_kernel<<<NBATCH * NWIN_Y, 128>>>(x, y, out);
}